// round 2
// baseline (speedup 1.0000x reference)
#include <cuda_runtime.h>
#include <cstdint>

#define B 8192
#define TC 512                 // tile cols
#define TR 128                 // tile rows
#define GX (B / TC)            // 16
#define GY (B / TR)            // 64
#define K2_BLOCKS 64

#define NEG_INF __int_as_float(0xff800000)
#define ENC_NEG_INF 0x007FFFFFu   // enc(-inf)

// Scratch (allocation-free rule: device globals). Re-initialized by k0 each launch.
__device__ unsigned g_rowmax[B];
__device__ unsigned g_colmax[B];
__device__ float    g_blocksum[K2_BLOCKS];

// Monotone float<->uint encoding so atomicMax(unsigned) == float max.
__device__ __forceinline__ unsigned enc(float f) {
    unsigned u = __float_as_uint(f);
    return u ^ ((unsigned)((int)u >> 31) | 0x80000000u);
}
__device__ __forceinline__ float dec(unsigned e) {
    unsigned u = (e & 0x80000000u) ? (e ^ 0x80000000u) : ~e;
    return __uint_as_float(u);
}

// ---------------------------------------------------------------------------
// K0: reset the global max arrays to enc(-inf). (Graph replays reuse globals.)
// ---------------------------------------------------------------------------
__global__ void wtl_k0() {
    int i = blockIdx.x * 1024 + threadIdx.x;  // 16 blocks x 1024 = 2*B
    if (i < B) g_rowmax[i] = ENC_NEG_INF;
    else       g_colmax[i - B] = ENC_NEG_INF;
}

// ---------------------------------------------------------------------------
// K1 tile body. Each of 8 warps sweeps full 512-col rows (4x LDG.128/lane),
// 16 row-iterations. DIAG path (64/1024 blocks) masks the diagonal element.
// ---------------------------------------------------------------------------
template<bool DIAG>
__device__ __forceinline__ void k1_body(const float* __restrict__ sim,
                                        int rowBase, int colBase,
                                        int tx, int ty, float* cm) {
    #pragma unroll 2
    for (int r = ty; r < TR; r += 8) {
        const int grow = rowBase + r;
        const float4* p =
            reinterpret_cast<const float4*>(sim + (size_t)grow * B + colBase) + tx;
        float4 v[4];
        #pragma unroll
        for (int j = 0; j < 4; j++) v[j] = p[j * 32];

        float rmax = NEG_INF;
        #pragma unroll
        for (int j = 0; j < 4; j++) {
            float e0 = v[j].x, e1 = v[j].y, e2 = v[j].z, e3 = v[j].w;
            if (DIAG) {
                const int gc = colBase + j * 128 + tx * 4;
                if (grow == gc + 0) e0 = NEG_INF;
                if (grow == gc + 1) e1 = NEG_INF;
                if (grow == gc + 2) e2 = NEG_INF;
                if (grow == gc + 3) e3 = NEG_INF;
            }
            cm[j * 4 + 0] = fmaxf(cm[j * 4 + 0], e0);
            cm[j * 4 + 1] = fmaxf(cm[j * 4 + 1], e1);
            cm[j * 4 + 2] = fmaxf(cm[j * 4 + 2], e2);
            cm[j * 4 + 3] = fmaxf(cm[j * 4 + 3], e3);
            rmax = fmaxf(rmax, fmaxf(fmaxf(e0, e1), fmaxf(e2, e3)));
        }
        #pragma unroll
        for (int o = 16; o > 0; o >>= 1)
            rmax = fmaxf(rmax, __shfl_xor_sync(0xffffffffu, rmax, o));
        if (tx == 0) atomicMax(&g_rowmax[grow], enc(rmax));
    }
}

__global__ void __launch_bounds__(256) wtl_k1(const float* __restrict__ sim) {
    const int tx = threadIdx.x;            // 0..31
    const int ty = threadIdx.y;            // 0..7
    const int colBase = blockIdx.x * TC;
    const int rowBase = blockIdx.y * TR;

    float cm[16];
    #pragma unroll
    for (int k = 0; k < 16; k++) cm[k] = NEG_INF;

    // Diagonal intersects this tile iff by/4 == bx (TR=128, TC=512).
    if ((blockIdx.y >> 2) == blockIdx.x)
        k1_body<true >(sim, rowBase, colBase, tx, ty, cm);
    else
        k1_body<false>(sim, rowBase, colBase, tx, ty, cm);

    // Column-max: fold 8 warp-rows via shared, then one atomic per column.
    __shared__ float s_col[8][TC];
    #pragma unroll
    for (int j = 0; j < 4; j++)
        *reinterpret_cast<float4*>(&s_col[ty][j * 128 + tx * 4]) =
            make_float4(cm[j * 4 + 0], cm[j * 4 + 1], cm[j * 4 + 2], cm[j * 4 + 3]);
    __syncthreads();

    const int tid = ty * 32 + tx;
    #pragma unroll
    for (int c = tid; c < TC; c += 256) {
        float m = s_col[0][c];
        #pragma unroll
        for (int s = 1; s < 8; s++) m = fmaxf(m, s_col[s][c]);
        atomicMax(&g_colmax[colBase + c], enc(m));
    }
}

// ---------------------------------------------------------------------------
// K2: per index i compute both half-losses, block-reduce. 64 blocks x 128.
// ---------------------------------------------------------------------------
__global__ void __launch_bounds__(128) wtl_k2(const float* __restrict__ sim) {
    const int i = blockIdx.x * 128 + threadIdx.x;

    const float pos = sim[(size_t)i * B + i];
    const float rm = dec(g_rowmax[i]);
    const float cx = dec(g_colmax[i]);

    const float pos_loss = fmaxf(0.2f * pos * pos - 0.7f * pos + 0.5f, 0.0f);

    float total = 0.0f;
    if (rm + 1.0f > pos)
        total += pos_loss + fmaxf(0.9f * rm * rm - 0.4f * rm + 0.03f, 0.0f);
    if (cx + 1.0f > pos)
        total += pos_loss + fmaxf(0.9f * cx * cx - 0.4f * cx + 0.03f, 0.0f);

    __shared__ float s_sum[128];
    s_sum[threadIdx.x] = total;
    __syncthreads();
    #pragma unroll
    for (int s = 64; s > 0; s >>= 1) {
        if (threadIdx.x < s) s_sum[threadIdx.x] += s_sum[threadIdx.x + s];
        __syncthreads();
    }
    if (threadIdx.x == 0) g_blocksum[blockIdx.x] = s_sum[0];
}

// ---------------------------------------------------------------------------
// K3: deterministic final fold of 64 block sums.
// ---------------------------------------------------------------------------
__global__ void wtl_k3(float* __restrict__ out) {
    float v = g_blocksum[threadIdx.x] + g_blocksum[threadIdx.x + 32];  // 32 threads
    #pragma unroll
    for (int o = 16; o > 0; o >>= 1)
        v += __shfl_xor_sync(0xffffffffu, v, o);
    if (threadIdx.x == 0) out[0] = v / (float)B;
}

extern "C" void kernel_launch(void* const* d_in, const int* in_sizes, int n_in,
                              void* d_out, int out_size) {
    const float* sim = (const float*)d_in[0];
    float* out = (float*)d_out;

    wtl_k0<<<16, 1024>>>();
    dim3 grid1(GX, GY);        // (16, 64)
    dim3 block1(32, 8);
    wtl_k1<<<grid1, block1>>>(sim);
    wtl_k2<<<K2_BLOCKS, 128>>>(sim);
    wtl_k3<<<1, 32>>>(out);
}